// round 4
// baseline (speedup 1.0000x reference)
#include <cuda_runtime.h>
#include <math.h>

#define BATCH 8
#define SEQ   256
#define F0    512
#define F1    256
#define F2    128
#define KMAX  30
#define PCB   16      // phaseC blocks per batch (8*16 = 128 blocks, one wave)
#define PCT   512     // threads per phaseC block (16 warps)
#define NSEG  32      // scanP segments (8 rows each), 32*8 = 256 blocks

// ---- scratch (__device__ globals; no allocations allowed) ----
__device__ float g_h[BATCH*SEQ*F1];
__device__ float g_z[BATCH*SEQ*F2];
__device__ float g_corr[BATCH*SEQ*SEQ];
__device__ float g_P[BATCH*SEQ*SEQ];       // 2-D inclusive prefix sums
__device__ float g_diag[BATCH][SEQ];       // diag of corr
__device__ float g_seg[BATCH][NSEG][SEQ];  // per-segment row-scan totals
__device__ float g_Cbuf[2][BATCH][SEQ];    // DP C-vector, double buffered
__device__ int   g_ctrS[BATCH];            // scanP barrier (epoch-based, never reset)
__device__ int   g_ctrC[BATCH][KMAX];      // phaseC barriers (epoch-based, never reset)
__device__ float g_part[BATCH][PCB][SEQ];  // per-block partial numerators

// ---- packed fp32x2 helpers (FFMA2: 2x fp32 FMA throughput) ----
__device__ __forceinline__ void ffma2(unsigned long long& d,
                                      unsigned long long a,
                                      unsigned long long b) {
    asm("fma.rn.f32x2 %0, %1, %2, %0;" : "+l"(d) : "l"(a), "l"(b));
}
__device__ __forceinline__ void unpack2(unsigned long long v, float& lo, float& hi) {
    asm("mov.b64 {%0,%1}, %2;" : "=f"(lo), "=f"(hi) : "l"(v));
}

// ============================================================
// GEMM: C[M,N] = (A[M,K] @ B[K,N]) + bias, optional relu.
// 64x64 tile, BK=16, 256 threads, 4x4 per thread via FFMA2.
// A stored duplicated in smem: As2[k][2m]=As2[k][2m+1]=A[m,k],
// so one LDS.128 yields two packed (a,a) operands.
// ============================================================
template<int RELU>
__global__ __launch_bounds__(256) void gemm_kernel(
    const float* __restrict__ A, const float* __restrict__ B,
    const float* __restrict__ bias, float* __restrict__ C,
    int M, int N, int K)
{
    __shared__ float As2[16][128];   // duplicated pairs
    __shared__ float Bs[16][64];
    const int m0 = blockIdx.y * 64, n0 = blockIdx.x * 64;
    const int tid = threadIdx.x;
    const int ty = tid >> 4, tx = tid & 15;
    const int arow = tid >> 2, akq = tid & 3;
    const int bkr  = tid >> 4, bnq = tid & 15;

    unsigned long long acc2[4][2] = {};

    for (int k0 = 0; k0 < K; k0 += 16) {
        float4 va = *(const float4*)(A + (size_t)(m0 + arow) * K + k0 + akq * 4);
        *(float2*)&As2[akq*4+0][2*arow] = make_float2(va.x, va.x);
        *(float2*)&As2[akq*4+1][2*arow] = make_float2(va.y, va.y);
        *(float2*)&As2[akq*4+2][2*arow] = make_float2(va.z, va.z);
        *(float2*)&As2[akq*4+3][2*arow] = make_float2(va.w, va.w);
        float4 vb = *(const float4*)(B + (size_t)(k0 + bkr) * N + n0 + bnq * 4);
        *(float4*)&Bs[bkr][bnq*4] = vb;
        __syncthreads();
        #pragma unroll
        for (int k = 0; k < 16; k++) {
            ulonglong2 a01 = *(const ulonglong2*)&As2[k][ty*8];      // (a0,a0),(a1,a1)
            ulonglong2 a23 = *(const ulonglong2*)&As2[k][ty*8 + 4];  // (a2,a2),(a3,a3)
            ulonglong2 bq  = *(const ulonglong2*)&Bs[k][tx*4];       // (b0,b1),(b2,b3)
            ffma2(acc2[0][0], a01.x, bq.x); ffma2(acc2[0][1], a01.x, bq.y);
            ffma2(acc2[1][0], a01.y, bq.x); ffma2(acc2[1][1], a01.y, bq.y);
            ffma2(acc2[2][0], a23.x, bq.x); ffma2(acc2[2][1], a23.x, bq.y);
            ffma2(acc2[3][0], a23.y, bq.x); ffma2(acc2[3][1], a23.y, bq.y);
        }
        __syncthreads();
    }

    #pragma unroll
    for (int r = 0; r < 4; r++) {
        int m = m0 + ty*4 + r;
        #pragma unroll
        for (int c2 = 0; c2 < 2; c2++) {
            float v0, v1;
            unpack2(acc2[r][c2], v0, v1);
            int n = n0 + tx*4 + c2*2;
            v0 += bias[n]; v1 += bias[n+1];
            if (RELU) { v0 = fmaxf(v0, 0.0f); v1 = fmaxf(v1, 0.0f); }
            *(float2*)(C + (size_t)m * N + n) = make_float2(v0, v1);
        }
    }
}

// ============================================================
// corr[b] = z_b @ z_b^T (NT, M=N=256, K=128) via FFMA2.
// Captures the diagonal into g_diag.
// ============================================================
__global__ __launch_bounds__(256) void syrk_kernel()
{
    __shared__ float As2[16][128];   // duplicated pairs
    __shared__ float Bs[16][64];
    const int bz = blockIdx.z;
    const float* Z = g_z + (size_t)bz * SEQ * F2;
    float* C = g_corr + (size_t)bz * SEQ * SEQ;
    const int m0 = blockIdx.y * 64, n0 = blockIdx.x * 64;
    const int tid = threadIdx.x;
    const int ty = tid >> 4, tx = tid & 15;
    const int row = tid >> 2, kq = tid & 3;

    unsigned long long acc2[4][2] = {};

    for (int k0 = 0; k0 < F2; k0 += 16) {
        float4 va = *(const float4*)(Z + (size_t)(m0 + row) * F2 + k0 + kq * 4);
        *(float2*)&As2[kq*4+0][2*row] = make_float2(va.x, va.x);
        *(float2*)&As2[kq*4+1][2*row] = make_float2(va.y, va.y);
        *(float2*)&As2[kq*4+2][2*row] = make_float2(va.z, va.z);
        *(float2*)&As2[kq*4+3][2*row] = make_float2(va.w, va.w);
        float4 vb = *(const float4*)(Z + (size_t)(n0 + row) * F2 + k0 + kq * 4);
        Bs[kq*4+0][row] = vb.x; Bs[kq*4+1][row] = vb.y;
        Bs[kq*4+2][row] = vb.z; Bs[kq*4+3][row] = vb.w;
        __syncthreads();
        #pragma unroll
        for (int k = 0; k < 16; k++) {
            ulonglong2 a01 = *(const ulonglong2*)&As2[k][ty*8];
            ulonglong2 a23 = *(const ulonglong2*)&As2[k][ty*8 + 4];
            ulonglong2 bq  = *(const ulonglong2*)&Bs[k][tx*4];
            ffma2(acc2[0][0], a01.x, bq.x); ffma2(acc2[0][1], a01.x, bq.y);
            ffma2(acc2[1][0], a01.y, bq.x); ffma2(acc2[1][1], a01.y, bq.y);
            ffma2(acc2[2][0], a23.x, bq.x); ffma2(acc2[2][1], a23.x, bq.y);
            ffma2(acc2[3][0], a23.y, bq.x); ffma2(acc2[3][1], a23.y, bq.y);
        }
        __syncthreads();
    }

    #pragma unroll
    for (int r = 0; r < 4; r++) {
        int m = m0 + ty*4 + r;
        #pragma unroll
        for (int c2 = 0; c2 < 2; c2++) {
            float v0, v1;
            unpack2(acc2[r][c2], v0, v1);
            int n = n0 + tx*4 + c2*2;
            C[(size_t)m * SEQ + n]     = v0;
            C[(size_t)m * SEQ + n + 1] = v1;
            if (m == n)     g_diag[bz][m] = v0;
            if (m == n + 1) g_diag[bz][m] = v1;
        }
    }
}

// ============================================================
// scanP: fused D + row-scan + col-scan -> P, one kernel.
// Block = (segment s of 8 rows, batch b), 256 threads.
// Phase 1: thread=column, 8-row D + running sum into smem.
// Epoch spin barrier across the 32 blocks of this batch.
// Phase 2: per-column segment offset. Phase 3: warp col-scan.
// ============================================================
__global__ __launch_bounds__(256) void scanP_kernel()
{
    __shared__ float T[8][SEQ];     // within-segment row-scan values
    __shared__ float off[SEQ];      // per-column offset from earlier segments
    __shared__ float sdn[8];
    const int s = blockIdx.x, b = blockIdx.y;
    const int tid = threadIdx.x;
    const int n0 = s * 8;
    const float* cb = g_corr + (size_t)b * SEQ * SEQ;

    if (tid < 8) sdn[tid] = g_diag[b][n0 + tid];
    const float di = g_diag[b][tid];
    __syncthreads();

    float run = 0.0f;
    #pragma unroll
    for (int n = 0; n < 8; n++) {
        float denom = sqrtf(fmaxf(sdn[n] * di, 1e-8f));
        float d = (1.0f - cb[(size_t)(n0 + n) * SEQ + tid] / denom) * 0.5f;
        run += d;
        T[n][tid] = run;
    }
    g_seg[b][s][tid] = run;
    __threadfence();                       // release g_seg writes
    __syncthreads();
    if (tid == 0) {
        int old = atomicAdd(&g_ctrS[b], 1);
        int target = (old / NSEG + 1) * NSEG;   // epoch-safe across graph replays
        volatile int* p = &g_ctrS[b];
        while (*p < target) { }
        __threadfence();
    }
    __syncthreads();

    float o = 0.0f;
    for (int sp = 0; sp < s; sp++) o += __ldcg(&g_seg[b][sp][tid]);
    off[tid] = o;
    __syncthreads();

    // Phase 3: warp w scans row n0+w along i
    const int w = tid >> 5, l = tid & 31;
    float v[8];
    #pragma unroll
    for (int j = 0; j < 8; j++) v[j] = T[w][l*8 + j] + off[l*8 + j];
    #pragma unroll
    for (int j = 1; j < 8; j++) v[j] += v[j-1];
    float tot = v[7], inc = tot;
    #pragma unroll
    for (int d2 = 1; d2 < 32; d2 <<= 1) {
        float t2 = __shfl_up_sync(0xffffffffu, inc, d2);
        if (l >= d2) inc += t2;
    }
    float excl = inc - tot;
    #pragma unroll
    for (int j = 0; j < 8; j++) v[j] += excl;
    float* P = g_P + ((size_t)b * SEQ + n0 + w) * SEQ;
    *(float4*)(P + l*8)     = make_float4(v[0], v[1], v[2], v[3]);
    *(float4*)(P + l*8 + 4) = make_float4(v[4], v[5], v[6], v[7]);
}

// ============================================================
// Phase C: 30-step DP across the chip (128 blocks, one wave).
// Warp owns row wb; its Ds row lives in 8 registers, computed
// once from P (sub-diagonal provably never read by the DP).
// C-vector staged to smem once per step.
// ============================================================
__global__ __launch_bounds__(PCT) void phaseC_kernel()
{
    __shared__ float s_acc[PCT/32][SEQ];
    __shared__ float s_C[SEQ];
    const int b = blockIdx.x, blk = blockIdx.y;
    const int tid = threadIdx.x, w = tid >> 5, l = tid & 31;
    const int wb = blk * (PCT/32) + w;
    const float* Pb = g_P + (size_t)b * SEQ * SEQ;

    // ---- build Ds row wb from the 4-corner formula ----
    float rowv[8];
    const int nm1 = wb - 1;
    const float dcorner = (wb == 0) ? 0.0f : Pb[nm1*SEQ + nm1];
    #pragma unroll
    for (int j = 0; j < 8; j++) {
        int i = l + 32*j;
        if (i >= wb) {
            float a  = Pb[i*SEQ + i];
            float bb = (wb == 0) ? 0.0f : Pb[nm1*SEQ + i];
            float cc = (wb == 0) ? 0.0f : Pb[i*SEQ + nm1];
            rowv[j] = ((a - bb) - cc) + dcorner;
        } else {
            rowv[j] = 3.0e38f;
        }
    }
    // publish k=0 init column (i == 255)
    if (l == 31) { g_Cbuf[0][b][wb] = rowv[7]; __threadfence(); }
    __syncthreads();
    if (tid == 0) {
        int old = atomicAdd(&g_ctrC[b][0], 1);
        int target = (old / PCB + 1) * PCB;
        volatile int* p = &g_ctrC[b][0];
        while (*p < target) { }
        __threadfence();
    }
    __syncthreads();
    if (tid < SEQ) s_C[tid] = __ldcg(&g_Cbuf[0][b][tid]);
    __syncthreads();

    float acc[8] = {};

    for (int kk = 1; kk < KMAX; kk++) {
        const int limit = SEQ - kk;
        if (wb < limit) {
            float t[8];
            float mn = 3.0e38f;
            #pragma unroll
            for (int j = 0; j < 8; j++) {
                int i = l + 32*j;
                float v = (i < limit) ? (rowv[j] + s_C[i + 1]) : 3.0e38f;
                t[j] = v;
                mn = fminf(mn, v);
            }
            #pragma unroll
            for (int off = 16; off > 0; off >>= 1)
                mn = fminf(mn, __shfl_xor_sync(0xffffffffu, mn, off));

            float e[8];
            float s = 0.0f;
            #pragma unroll
            for (int j = 0; j < 8; j++) {
                e[j] = __expf(mn - t[j]);   // invalid lanes -> exp(-huge) = 0
                s += e[j];
            }
            #pragma unroll
            for (int off = 16; off > 0; off >>= 1)
                s += __shfl_xor_sync(0xffffffffu, s, off);

            float inv = __fdividef(1.0f, s);
            #pragma unroll
            for (int j = 0; j < 8; j++) acc[j] += e[j] * inv;

            if (l == 0) { g_Cbuf[kk & 1][b][wb] = mn; __threadfence(); }
        }

        __syncthreads();
        if (tid == 0) {
            int old = atomicAdd(&g_ctrC[b][kk], 1);
            int target = (old / PCB + 1) * PCB;
            volatile int* p = &g_ctrC[b][kk];
            while (*p < target) { }
            __threadfence();
        }
        __syncthreads();
        if (tid < SEQ) s_C[tid] = __ldcg(&g_Cbuf[kk & 1][b][tid]);
        __syncthreads();
    }

    #pragma unroll
    for (int j = 0; j < 8; j++) s_acc[w][l + 32*j] = acc[j];
    __syncthreads();
    if (tid < SEQ) {
        float sum = 0.0f;
        #pragma unroll
        for (int ww = 0; ww < PCT/32; ww++) sum += s_acc[ww][tid];
        g_part[b][blk][tid] = sum;
    }
}

// out[b][i] = (sum of partials + k0 term) / exact mask count
__global__ __launch_bounds__(256) void finalize_kernel(float* __restrict__ out)
{
    const int b = blockIdx.x, i = threadIdx.x;
    float num = (i == SEQ - 1) ? (float)SEQ : 0.0f;
    #pragma unroll
    for (int p = 0; p < PCB; p++) num += g_part[b][p][i];
    int m = min(KMAX - 1, SEQ - 1 - i);
    float cnt = (float)((i + 1) * m + ((i == SEQ - 1) ? SEQ : 0));
    out[b*SEQ + i] = num / cnt;
}

// ============================================================
extern "C" void kernel_launch(void* const* d_in, const int* in_sizes, int n_in,
                              void* d_out, int out_size)
{
    const float* x  = (const float*)d_in[0];
    const float* W0 = (const float*)d_in[1];
    const float* b0 = (const float*)d_in[2];
    const float* W1 = (const float*)d_in[3];
    const float* b1 = (const float*)d_in[4];
    float* out = (float*)d_out;

    static float* p_h = nullptr;
    static float* p_z = nullptr;
    if (!p_h) {
        cudaGetSymbolAddress((void**)&p_h, g_h);
        cudaGetSymbolAddress((void**)&p_z, g_z);
    }

    gemm_kernel<1><<<dim3(F1/64, (BATCH*SEQ)/64), 256>>>(x,   W0, b0, p_h, BATCH*SEQ, F1, F0);
    gemm_kernel<0><<<dim3(F2/64, (BATCH*SEQ)/64), 256>>>(p_h, W1, b1, p_z, BATCH*SEQ, F2, F1);
    syrk_kernel    <<<dim3(SEQ/64, SEQ/64, BATCH), 256>>>();
    scanP_kernel   <<<dim3(NSEG, BATCH), 256>>>();
    phaseC_kernel  <<<dim3(BATCH, PCB), PCT>>>();
    finalize_kernel<<<BATCH, SEQ>>>(out);
}

// round 5
// speedup vs baseline: 1.0277x; 1.0277x over previous
#include <cuda_runtime.h>
#include <math.h>

#define BATCH 8
#define SEQ   256
#define F0    512
#define F1    256
#define F2    128
#define KMAX  30
#define PCB   16      // phaseC blocks per batch (8*16 = 128 blocks, one wave)
#define PCT   512     // threads per phaseC block (16 warps)
#define NSEG  32      // scanP segments (8 rows each), 32*8 = 256 blocks

// ---- scratch (__device__ globals; no allocations allowed) ----
__device__ float g_h[BATCH*SEQ*F1];
__device__ float g_z[BATCH*SEQ*F2];
__device__ float g_corr[BATCH*SEQ*SEQ];
__device__ float g_P[BATCH*SEQ*SEQ];        // 2-D inclusive prefix sums
__device__ float g_diag[BATCH][SEQ];        // diag of corr
__device__ float g_seg[BATCH][NSEG][SEQ];   // per-segment row-scan totals
__device__ float g_C[KMAX][BATCH][SEQ+1];   // DP C-vectors (clipped), [256]=0
__device__ int   g_ctrS[BATCH];             // scanP barrier (epoch counters, never reset)
__device__ int   g_ctrC[BATCH][KMAX];       // phaseC barriers (epoch counters, never reset)
__device__ float g_part[BATCH][PCB][SEQ];   // per-block partial numerators

// ---- packed fp32x2 helpers (FFMA2: 2x fp32 FMA throughput) ----
__device__ __forceinline__ void ffma2(unsigned long long& d,
                                      unsigned long long a,
                                      unsigned long long b) {
    asm("fma.rn.f32x2 %0, %1, %2, %0;" : "+l"(d) : "l"(a), "l"(b));
}
__device__ __forceinline__ void unpack2(unsigned long long v, float& lo, float& hi) {
    asm("mov.b64 {%0,%1}, %2;" : "=f"(lo), "=f"(hi) : "l"(v));
}

// Cross-block barrier: call from tid==0 only, AFTER __syncthreads(),
// and __syncthreads() again after it returns. Cumulative fences make the
// tid0-only release/acquire cover the whole block's prior writes.
__device__ __forceinline__ void gbar(int* ctr, int nblk) {
    __threadfence();                       // release (cumulative)
    int old = atomicAdd(ctr, 1);
    int target = (old / nblk + 1) * nblk;  // epoch-safe across graph replays
    volatile int* p = ctr;
    while (*p < target) { }
    __threadfence();                       // acquire (cumulative)
}

// ============================================================
// GEMM: C[M,N] = (A[M,K] @ B[K,N]) + bias, optional relu.
// 64x64 tile, BK=16, 256 threads, 4x4 per thread via FFMA2.
// ============================================================
template<int RELU>
__global__ __launch_bounds__(256) void gemm_kernel(
    const float* __restrict__ A, const float* __restrict__ B,
    const float* __restrict__ bias, float* __restrict__ C,
    int M, int N, int K)
{
    __shared__ float As2[16][128];   // duplicated pairs
    __shared__ float Bs[16][64];
    const int m0 = blockIdx.y * 64, n0 = blockIdx.x * 64;
    const int tid = threadIdx.x;
    const int ty = tid >> 4, tx = tid & 15;
    const int arow = tid >> 2, akq = tid & 3;
    const int bkr  = tid >> 4, bnq = tid & 15;

    unsigned long long acc2[4][2] = {};

    for (int k0 = 0; k0 < K; k0 += 16) {
        float4 va = *(const float4*)(A + (size_t)(m0 + arow) * K + k0 + akq * 4);
        *(float2*)&As2[akq*4+0][2*arow] = make_float2(va.x, va.x);
        *(float2*)&As2[akq*4+1][2*arow] = make_float2(va.y, va.y);
        *(float2*)&As2[akq*4+2][2*arow] = make_float2(va.z, va.z);
        *(float2*)&As2[akq*4+3][2*arow] = make_float2(va.w, va.w);
        float4 vb = *(const float4*)(B + (size_t)(k0 + bkr) * N + n0 + bnq * 4);
        *(float4*)&Bs[bkr][bnq*4] = vb;
        __syncthreads();
        #pragma unroll
        for (int k = 0; k < 16; k++) {
            ulonglong2 a01 = *(const ulonglong2*)&As2[k][ty*8];
            ulonglong2 a23 = *(const ulonglong2*)&As2[k][ty*8 + 4];
            ulonglong2 bq  = *(const ulonglong2*)&Bs[k][tx*4];
            ffma2(acc2[0][0], a01.x, bq.x); ffma2(acc2[0][1], a01.x, bq.y);
            ffma2(acc2[1][0], a01.y, bq.x); ffma2(acc2[1][1], a01.y, bq.y);
            ffma2(acc2[2][0], a23.x, bq.x); ffma2(acc2[2][1], a23.x, bq.y);
            ffma2(acc2[3][0], a23.y, bq.x); ffma2(acc2[3][1], a23.y, bq.y);
        }
        __syncthreads();
    }

    #pragma unroll
    for (int r = 0; r < 4; r++) {
        int m = m0 + ty*4 + r;
        #pragma unroll
        for (int c2 = 0; c2 < 2; c2++) {
            float v0, v1;
            unpack2(acc2[r][c2], v0, v1);
            int n = n0 + tx*4 + c2*2;
            v0 += bias[n]; v1 += bias[n+1];
            if (RELU) { v0 = fmaxf(v0, 0.0f); v1 = fmaxf(v1, 0.0f); }
            *(float2*)(C + (size_t)m * N + n) = make_float2(v0, v1);
        }
    }
}

// ============================================================
// corr[b] = z_b @ z_b^T (NT, M=N=256, K=128) via FFMA2 + diag capture.
// ============================================================
__global__ __launch_bounds__(256) void syrk_kernel()
{
    __shared__ float As2[16][128];
    __shared__ float Bs[16][64];
    const int bz = blockIdx.z;
    const float* Z = g_z + (size_t)bz * SEQ * F2;
    float* C = g_corr + (size_t)bz * SEQ * SEQ;
    const int m0 = blockIdx.y * 64, n0 = blockIdx.x * 64;
    const int tid = threadIdx.x;
    const int ty = tid >> 4, tx = tid & 15;
    const int row = tid >> 2, kq = tid & 3;

    unsigned long long acc2[4][2] = {};

    for (int k0 = 0; k0 < F2; k0 += 16) {
        float4 va = *(const float4*)(Z + (size_t)(m0 + row) * F2 + k0 + kq * 4);
        *(float2*)&As2[kq*4+0][2*row] = make_float2(va.x, va.x);
        *(float2*)&As2[kq*4+1][2*row] = make_float2(va.y, va.y);
        *(float2*)&As2[kq*4+2][2*row] = make_float2(va.z, va.z);
        *(float2*)&As2[kq*4+3][2*row] = make_float2(va.w, va.w);
        float4 vb = *(const float4*)(Z + (size_t)(n0 + row) * F2 + k0 + kq * 4);
        Bs[kq*4+0][row] = vb.x; Bs[kq*4+1][row] = vb.y;
        Bs[kq*4+2][row] = vb.z; Bs[kq*4+3][row] = vb.w;
        __syncthreads();
        #pragma unroll
        for (int k = 0; k < 16; k++) {
            ulonglong2 a01 = *(const ulonglong2*)&As2[k][ty*8];
            ulonglong2 a23 = *(const ulonglong2*)&As2[k][ty*8 + 4];
            ulonglong2 bq  = *(const ulonglong2*)&Bs[k][tx*4];
            ffma2(acc2[0][0], a01.x, bq.x); ffma2(acc2[0][1], a01.x, bq.y);
            ffma2(acc2[1][0], a01.y, bq.x); ffma2(acc2[1][1], a01.y, bq.y);
            ffma2(acc2[2][0], a23.x, bq.x); ffma2(acc2[2][1], a23.x, bq.y);
            ffma2(acc2[3][0], a23.y, bq.x); ffma2(acc2[3][1], a23.y, bq.y);
        }
        __syncthreads();
    }

    #pragma unroll
    for (int r = 0; r < 4; r++) {
        int m = m0 + ty*4 + r;
        #pragma unroll
        for (int c2 = 0; c2 < 2; c2++) {
            float v0, v1;
            unpack2(acc2[r][c2], v0, v1);
            int n = n0 + tx*4 + c2*2;
            C[(size_t)m * SEQ + n]     = v0;
            C[(size_t)m * SEQ + n + 1] = v1;
            if (m == n)     g_diag[bz][m] = v0;
            if (m == n + 1) g_diag[bz][m] = v1;
        }
    }
}

// ============================================================
// scanP: fused D + row-scan + col-scan -> P (one kernel).
// ============================================================
__global__ __launch_bounds__(256) void scanP_kernel()
{
    __shared__ float T[8][SEQ];
    __shared__ float off[SEQ];
    __shared__ float sdn[8];
    const int s = blockIdx.x, b = blockIdx.y;
    const int tid = threadIdx.x;
    const int n0 = s * 8;
    const float* cb = g_corr + (size_t)b * SEQ * SEQ;

    if (tid < 8) sdn[tid] = g_diag[b][n0 + tid];
    const float di = g_diag[b][tid];
    __syncthreads();

    float run = 0.0f;
    #pragma unroll
    for (int n = 0; n < 8; n++) {
        float denom = sqrtf(fmaxf(sdn[n] * di, 1e-8f));
        float d = (1.0f - cb[(size_t)(n0 + n) * SEQ + tid] / denom) * 0.5f;
        run += d;
        T[n][tid] = run;
    }
    g_seg[b][s][tid] = run;
    __syncthreads();
    if (tid == 0) gbar(&g_ctrS[b], NSEG);
    __syncthreads();

    float o = 0.0f;
    for (int sp = 0; sp < s; sp++) o += __ldcg(&g_seg[b][sp][tid]);
    off[tid] = o;
    __syncthreads();

    const int w = tid >> 5, l = tid & 31;
    float v[8];
    #pragma unroll
    for (int j = 0; j < 8; j++) v[j] = T[w][l*8 + j] + off[l*8 + j];
    #pragma unroll
    for (int j = 1; j < 8; j++) v[j] += v[j-1];
    float tot = v[7], inc = tot;
    #pragma unroll
    for (int d2 = 1; d2 < 32; d2 <<= 1) {
        float t2 = __shfl_up_sync(0xffffffffu, inc, d2);
        if (l >= d2) inc += t2;
    }
    float excl = inc - tot;
    #pragma unroll
    for (int j = 0; j < 8; j++) v[j] += excl;
    float* P = g_P + ((size_t)b * SEQ + n0 + w) * SEQ;
    *(float4*)(P + l*8)     = make_float4(v[0], v[1], v[2], v[3]);
    *(float4*)(P + l*8 + 4) = make_float4(v[4], v[5], v[6], v[7]);
}

// ============================================================
// Phase C (merged): min-only barrier loop, C table staged into
// persistent smem, then barrier-free softmax accumulation.
// grid (BATCH, PCB), 512 threads, warp owns row wb (regs).
// ============================================================
__global__ __launch_bounds__(PCT) void phaseC_kernel()
{
    __shared__ float sC[KMAX][SEQ + 2];     // staged C vectors, ~30.9KB
    __shared__ float s_acc[PCT/32][SEQ];    // 16KB
    const int b = blockIdx.x, blk = blockIdx.y;
    const int tid = threadIdx.x, w = tid >> 5, l = tid & 31;
    const int wb = blk * (PCT/32) + w;      // row id within batch
    const float* Pb = g_P + (size_t)b * SEQ * SEQ;

    // ---- build Ds row wb from the 4-corner formula (regs) ----
    float rowv[8];
    const int nm1 = wb - 1;
    const float dcorner = (wb == 0) ? 0.0f : Pb[nm1*SEQ + nm1];
    #pragma unroll
    for (int j = 0; j < 8; j++) {
        int i = l + 32*j;
        if (i >= wb) {
            float a  = Pb[i*SEQ + i];
            float bb = (wb == 0) ? 0.0f : Pb[nm1*SEQ + i];
            float cc = (wb == 0) ? 0.0f : Pb[i*SEQ + nm1];
            rowv[j] = ((a - bb) - cc) + dcorner;
        } else {
            rowv[j] = 3.0e38f;
        }
    }
    // publish C[0] (unclipped init column i=255)
    if (l == 31) g_C[0][b][wb] = rowv[7];
    if (tid == 0) g_C[0][b][SEQ] = 0.0f;
    __syncthreads();
    if (tid == 0) gbar(&g_ctrC[b][0], PCB);
    __syncthreads();
    if (tid <= SEQ) sC[0][tid] = __ldcg(&g_C[0][b][tid]);
    __syncthreads();

    // ---- min-only DP loop (30 cross-block barriers total) ----
    for (int kk = 1; kk < KMAX; kk++) {
        const int limit = SEQ - kk;
        if (wb < limit) {
            float mn = 3.0e38f;
            #pragma unroll
            for (int j = 0; j < 8; j++) {
                int i = l + 32*j;
                float t = (i < limit) ? (rowv[j] + sC[kk-1][i + 1]) : 3.0e38f;
                mn = fminf(mn, t);
            }
            #pragma unroll
            for (int off = 16; off > 0; off >>= 1)
                mn = fminf(mn, __shfl_xor_sync(0xffffffffu, mn, off));
            if (l == 0) g_C[kk][b][wb] = mn;            // wb<limit: unclipped min
        } else {
            if (l == 0) g_C[kk][b][wb] = 0.0f;          // clipped region
        }
        if (tid == 0) g_C[kk][b][SEQ] = 0.0f;
        __syncthreads();
        if (tid == 0) gbar(&g_ctrC[b][kk], PCB);
        __syncthreads();
        if (tid <= SEQ) sC[kk][tid] = __ldcg(&g_C[kk][b][tid]);
        __syncthreads();
    }

    // ---- barrier-free softmax accumulation from smem ----
    float acc[8] = {};
    for (int kk = 1; kk < KMAX; kk++) {
        const int limit = SEQ - kk;
        if (wb >= limit) break;
        const float mn = sC[kk][wb];
        float e[8];
        float s = 0.0f;
        #pragma unroll
        for (int j = 0; j < 8; j++) {
            int i = l + 32*j;
            float t = (i < limit) ? (rowv[j] + sC[kk-1][i + 1]) : 3.0e38f;
            e[j] = __expf(mn - t);      // invalid / i<wb lanes -> 0
            s += e[j];
        }
        #pragma unroll
        for (int off = 16; off > 0; off >>= 1)
            s += __shfl_xor_sync(0xffffffffu, s, off);
        float inv = __fdividef(1.0f, s);
        #pragma unroll
        for (int j = 0; j < 8; j++) acc[j] += e[j] * inv;
    }

    #pragma unroll
    for (int j = 0; j < 8; j++) s_acc[w][l + 32*j] = acc[j];
    __syncthreads();
    if (tid < SEQ) {
        float sum = 0.0f;
        #pragma unroll
        for (int ww = 0; ww < PCT/32; ww++) sum += s_acc[ww][tid];
        g_part[b][blk][tid] = sum;
    }
}

// out[b][i] = (sum of partials + k0 term) / exact mask count
__global__ __launch_bounds__(256) void finalize_kernel(float* __restrict__ out)
{
    const int b = blockIdx.x, i = threadIdx.x;
    float num = (i == SEQ - 1) ? (float)SEQ : 0.0f;
    #pragma unroll
    for (int p = 0; p < PCB; p++) num += g_part[b][p][i];
    int m = min(KMAX - 1, SEQ - 1 - i);
    float cnt = (float)((i + 1) * m + ((i == SEQ - 1) ? SEQ : 0));
    out[b*SEQ + i] = num / cnt;
}

// ============================================================
extern "C" void kernel_launch(void* const* d_in, const int* in_sizes, int n_in,
                              void* d_out, int out_size)
{
    const float* x  = (const float*)d_in[0];
    const float* W0 = (const float*)d_in[1];
    const float* b0 = (const float*)d_in[2];
    const float* W1 = (const float*)d_in[3];
    const float* b1 = (const float*)d_in[4];
    float* out = (float*)d_out;

    static float* p_h = nullptr;
    static float* p_z = nullptr;
    if (!p_h) {
        cudaGetSymbolAddress((void**)&p_h, g_h);
        cudaGetSymbolAddress((void**)&p_z, g_z);
    }

    gemm_kernel<1><<<dim3(F1/64, (BATCH*SEQ)/64), 256>>>(x,   W0, b0, p_h, BATCH*SEQ, F1, F0);
    gemm_kernel<0><<<dim3(F2/64, (BATCH*SEQ)/64), 256>>>(p_h, W1, b1, p_z, BATCH*SEQ, F2, F1);
    syrk_kernel    <<<dim3(SEQ/64, SEQ/64, BATCH), 256>>>();
    scanP_kernel   <<<dim3(NSEG, BATCH), 256>>>();
    phaseC_kernel  <<<dim3(BATCH, PCB), PCT>>>();
    finalize_kernel<<<BATCH, SEQ>>>(out);
}

// round 6
// speedup vs baseline: 1.0692x; 1.0404x over previous
#include <cuda_runtime.h>
#include <math.h>

#define BATCH 8
#define SEQ   256
#define F0    512
#define F1    256
#define F2    128
#define KMAX  30
#define PCB   16      // phaseC blocks per batch (8*16 = 128 blocks, one wave)
#define PCT   512     // threads per phaseC block (16 warps)
#define NSEG  32      // scanP segments (8 rows each), 32*8 = 256 blocks

// ---- scratch (__device__ globals; no allocations allowed) ----
__device__ float g_h[BATCH*SEQ*F1];
__device__ float g_z[BATCH*SEQ*F2];
__device__ float g_corr[BATCH*SEQ*SEQ];
__device__ float g_P[BATCH*SEQ*SEQ];        // 2-D inclusive prefix sums
__device__ float g_diag[BATCH][SEQ];        // diag of corr
__device__ float g_seg[BATCH][NSEG][SEQ];   // per-segment row-scan totals
__device__ float g_C[KMAX][BATCH][SEQ+1];   // DP C-vectors (clipped), [256]=0
__device__ int   g_ctrS[BATCH];             // scanP barrier (epoch counters, never reset)
__device__ int   g_ctrC[BATCH][KMAX];       // phaseC barriers (epoch counters, never reset)
__device__ float g_part[BATCH][PCB][SEQ];   // per-block partial numerators

// ---- packed fp32x2 helpers (FFMA2: 2x fp32 FMA throughput) ----
__device__ __forceinline__ void ffma2(unsigned long long& d,
                                      unsigned long long a,
                                      unsigned long long b) {
    asm("fma.rn.f32x2 %0, %1, %2, %0;" : "+l"(d) : "l"(a), "l"(b));
}
__device__ __forceinline__ void unpack2(unsigned long long v, float& lo, float& hi) {
    asm("mov.b64 {%0,%1}, %2;" : "=f"(lo), "=f"(hi) : "l"(v));
}

// Cross-block barrier: call from tid==0 only, AFTER __syncthreads(),
// and __syncthreads() again after it returns. Cumulative fences make the
// tid0-only release/acquire cover the whole block's prior writes.
__device__ __forceinline__ void gbar(int* ctr, int nblk) {
    __threadfence();                       // release (cumulative)
    int old = atomicAdd(ctr, 1);
    int target = (old / nblk + 1) * nblk;  // epoch-safe across graph replays
    volatile int* p = ctr;
    while (*p < target) { }
    __threadfence();                       // acquire (cumulative)
}

// ============================================================
// GEMM: C[M,N] = (A[M,K] @ B[K,N]) + bias, optional relu.
// 64x64 tile, BK=16, 256 threads, 4x4 per thread via FFMA2.
// ============================================================
template<int RELU>
__global__ __launch_bounds__(256) void gemm_kernel(
    const float* __restrict__ A, const float* __restrict__ B,
    const float* __restrict__ bias, float* __restrict__ C,
    int M, int N, int K)
{
    __shared__ float As2[16][128];   // duplicated pairs
    __shared__ float Bs[16][64];
    const int m0 = blockIdx.y * 64, n0 = blockIdx.x * 64;
    const int tid = threadIdx.x;
    const int ty = tid >> 4, tx = tid & 15;
    const int arow = tid >> 2, akq = tid & 3;
    const int bkr  = tid >> 4, bnq = tid & 15;

    unsigned long long acc2[4][2] = {};

    for (int k0 = 0; k0 < K; k0 += 16) {
        float4 va = *(const float4*)(A + (size_t)(m0 + arow) * K + k0 + akq * 4);
        *(float2*)&As2[akq*4+0][2*arow] = make_float2(va.x, va.x);
        *(float2*)&As2[akq*4+1][2*arow] = make_float2(va.y, va.y);
        *(float2*)&As2[akq*4+2][2*arow] = make_float2(va.z, va.z);
        *(float2*)&As2[akq*4+3][2*arow] = make_float2(va.w, va.w);
        float4 vb = *(const float4*)(B + (size_t)(k0 + bkr) * N + n0 + bnq * 4);
        *(float4*)&Bs[bkr][bnq*4] = vb;
        __syncthreads();
        #pragma unroll
        for (int k = 0; k < 16; k++) {
            ulonglong2 a01 = *(const ulonglong2*)&As2[k][ty*8];
            ulonglong2 a23 = *(const ulonglong2*)&As2[k][ty*8 + 4];
            ulonglong2 bq  = *(const ulonglong2*)&Bs[k][tx*4];
            ffma2(acc2[0][0], a01.x, bq.x); ffma2(acc2[0][1], a01.x, bq.y);
            ffma2(acc2[1][0], a01.y, bq.x); ffma2(acc2[1][1], a01.y, bq.y);
            ffma2(acc2[2][0], a23.x, bq.x); ffma2(acc2[2][1], a23.x, bq.y);
            ffma2(acc2[3][0], a23.y, bq.x); ffma2(acc2[3][1], a23.y, bq.y);
        }
        __syncthreads();
    }

    #pragma unroll
    for (int r = 0; r < 4; r++) {
        int m = m0 + ty*4 + r;
        #pragma unroll
        for (int c2 = 0; c2 < 2; c2++) {
            float v0, v1;
            unpack2(acc2[r][c2], v0, v1);
            int n = n0 + tx*4 + c2*2;
            v0 += bias[n]; v1 += bias[n+1];
            if (RELU) { v0 = fmaxf(v0, 0.0f); v1 = fmaxf(v1, 0.0f); }
            *(float2*)(C + (size_t)m * N + n) = make_float2(v0, v1);
        }
    }
}

// ============================================================
// corr[b] = z_b @ z_b^T (NT, M=N=256, K=128) via FFMA2 + diag capture.
// ============================================================
__global__ __launch_bounds__(256) void syrk_kernel()
{
    __shared__ float As2[16][128];
    __shared__ float Bs[16][64];
    const int bz = blockIdx.z;
    const float* Z = g_z + (size_t)bz * SEQ * F2;
    float* C = g_corr + (size_t)bz * SEQ * SEQ;
    const int m0 = blockIdx.y * 64, n0 = blockIdx.x * 64;
    const int tid = threadIdx.x;
    const int ty = tid >> 4, tx = tid & 15;
    const int row = tid >> 2, kq = tid & 3;

    unsigned long long acc2[4][2] = {};

    for (int k0 = 0; k0 < F2; k0 += 16) {
        float4 va = *(const float4*)(Z + (size_t)(m0 + row) * F2 + k0 + kq * 4);
        *(float2*)&As2[kq*4+0][2*row] = make_float2(va.x, va.x);
        *(float2*)&As2[kq*4+1][2*row] = make_float2(va.y, va.y);
        *(float2*)&As2[kq*4+2][2*row] = make_float2(va.z, va.z);
        *(float2*)&As2[kq*4+3][2*row] = make_float2(va.w, va.w);
        float4 vb = *(const float4*)(Z + (size_t)(n0 + row) * F2 + k0 + kq * 4);
        Bs[kq*4+0][row] = vb.x; Bs[kq*4+1][row] = vb.y;
        Bs[kq*4+2][row] = vb.z; Bs[kq*4+3][row] = vb.w;
        __syncthreads();
        #pragma unroll
        for (int k = 0; k < 16; k++) {
            ulonglong2 a01 = *(const ulonglong2*)&As2[k][ty*8];
            ulonglong2 a23 = *(const ulonglong2*)&As2[k][ty*8 + 4];
            ulonglong2 bq  = *(const ulonglong2*)&Bs[k][tx*4];
            ffma2(acc2[0][0], a01.x, bq.x); ffma2(acc2[0][1], a01.x, bq.y);
            ffma2(acc2[1][0], a01.y, bq.x); ffma2(acc2[1][1], a01.y, bq.y);
            ffma2(acc2[2][0], a23.x, bq.x); ffma2(acc2[2][1], a23.x, bq.y);
            ffma2(acc2[3][0], a23.y, bq.x); ffma2(acc2[3][1], a23.y, bq.y);
        }
        __syncthreads();
    }

    #pragma unroll
    for (int r = 0; r < 4; r++) {
        int m = m0 + ty*4 + r;
        #pragma unroll
        for (int c2 = 0; c2 < 2; c2++) {
            float v0, v1;
            unpack2(acc2[r][c2], v0, v1);
            int n = n0 + tx*4 + c2*2;
            C[(size_t)m * SEQ + n]     = v0;
            C[(size_t)m * SEQ + n + 1] = v1;
            if (m == n)     g_diag[bz][m] = v0;
            if (m == n + 1) g_diag[bz][m] = v1;
        }
    }
}

// ============================================================
// scanP: fused D + row-scan + col-scan -> P (one kernel).
// ============================================================
__global__ __launch_bounds__(256) void scanP_kernel()
{
    __shared__ float T[8][SEQ];
    __shared__ float off[SEQ];
    __shared__ float sdn[8];
    const int s = blockIdx.x, b = blockIdx.y;
    const int tid = threadIdx.x;
    const int n0 = s * 8;
    const float* cb = g_corr + (size_t)b * SEQ * SEQ;

    if (tid < 8) sdn[tid] = g_diag[b][n0 + tid];
    const float di = g_diag[b][tid];
    __syncthreads();

    float run = 0.0f;
    #pragma unroll
    for (int n = 0; n < 8; n++) {
        float denom = sqrtf(fmaxf(sdn[n] * di, 1e-8f));
        float d = (1.0f - cb[(size_t)(n0 + n) * SEQ + tid] / denom) * 0.5f;
        run += d;
        T[n][tid] = run;
    }
    g_seg[b][s][tid] = run;
    __syncthreads();
    if (tid == 0) gbar(&g_ctrS[b], NSEG);
    __syncthreads();

    float o = 0.0f;
    for (int sp = 0; sp < s; sp++) o += __ldcg(&g_seg[b][sp][tid]);
    off[tid] = o;
    __syncthreads();

    const int w = tid >> 5, l = tid & 31;
    float v[8];
    #pragma unroll
    for (int j = 0; j < 8; j++) v[j] = T[w][l*8 + j] + off[l*8 + j];
    #pragma unroll
    for (int j = 1; j < 8; j++) v[j] += v[j-1];
    float tot = v[7], inc = tot;
    #pragma unroll
    for (int d2 = 1; d2 < 32; d2 <<= 1) {
        float t2 = __shfl_up_sync(0xffffffffu, inc, d2);
        if (l >= d2) inc += t2;
    }
    float excl = inc - tot;
    #pragma unroll
    for (int j = 0; j < 8; j++) v[j] += excl;
    float* P = g_P + ((size_t)b * SEQ + n0 + w) * SEQ;
    *(float4*)(P + l*8)     = make_float4(v[0], v[1], v[2], v[3]);
    *(float4*)(P + l*8 + 4) = make_float4(v[4], v[5], v[6], v[7]);
}

// ============================================================
// Phase C (merged): min-only barrier loop, C table staged into
// persistent smem, then barrier-free softmax accumulation.
// grid (BATCH, PCB), 512 threads, warp owns row wb (regs).
// ============================================================
__global__ __launch_bounds__(PCT) void phaseC_kernel()
{
    __shared__ float sC[KMAX][SEQ + 2];     // staged C vectors, ~30.9KB
    __shared__ float s_acc[PCT/32][SEQ];    // 16KB
    const int b = blockIdx.x, blk = blockIdx.y;
    const int tid = threadIdx.x, w = tid >> 5, l = tid & 31;
    const int wb = blk * (PCT/32) + w;      // row id within batch
    const float* Pb = g_P + (size_t)b * SEQ * SEQ;

    // ---- build Ds row wb from the 4-corner formula (regs) ----
    float rowv[8];
    const int nm1 = wb - 1;
    const float dcorner = (wb == 0) ? 0.0f : Pb[nm1*SEQ + nm1];
    #pragma unroll
    for (int j = 0; j < 8; j++) {
        int i = l + 32*j;
        if (i >= wb) {
            float a  = Pb[i*SEQ + i];
            float bb = (wb == 0) ? 0.0f : Pb[nm1*SEQ + i];
            float cc = (wb == 0) ? 0.0f : Pb[i*SEQ + nm1];
            rowv[j] = ((a - bb) - cc) + dcorner;
        } else {
            rowv[j] = 3.0e38f;
        }
    }
    // publish C[0] (unclipped init column i=255)
    if (l == 31) g_C[0][b][wb] = rowv[7];
    if (tid == 0) g_C[0][b][SEQ] = 0.0f;
    __syncthreads();
    if (tid == 0) gbar(&g_ctrC[b][0], PCB);
    __syncthreads();
    if (tid <= SEQ) sC[0][tid] = __ldcg(&g_C[0][b][tid]);
    __syncthreads();

    // ---- min-only DP loop (30 cross-block barriers total) ----
    for (int kk = 1; kk < KMAX; kk++) {
        const int limit = SEQ - kk;
        if (wb < limit) {
            float mn = 3.0e38f;
            #pragma unroll
            for (int j = 0; j < 8; j++) {
                int i = l + 32*j;
                float t = (i < limit) ? (rowv[j] + sC[kk-1][i + 1]) : 3.0e38f;
                mn = fminf(mn, t);
            }
            #pragma unroll
            for (int off = 16; off > 0; off >>= 1)
                mn = fminf(mn, __shfl_xor_sync(0xffffffffu, mn, off));
            if (l == 0) g_C[kk][b][wb] = mn;            // wb<limit: unclipped min
        } else {
            if (l == 0) g_C[kk][b][wb] = 0.0f;          // clipped region
        }
        if (tid == 0) g_C[kk][b][SEQ] = 0.0f;
        __syncthreads();
        if (tid == 0) gbar(&g_ctrC[b][kk], PCB);
        __syncthreads();
        if (tid <= SEQ) sC[kk][tid] = __ldcg(&g_C[kk][b][tid]);
        __syncthreads();
    }

    // ---- barrier-free softmax accumulation from smem ----
    float acc[8] = {};
    for (int kk = 1; kk < KMAX; kk++) {
        const int limit = SEQ - kk;
        if (wb >= limit) break;
        const float mn = sC[kk][wb];
        float e[8];
        float s = 0.0f;
        #pragma unroll
        for (int j = 0; j < 8; j++) {
            int i = l + 32*j;
            float t = (i < limit) ? (rowv[j] + sC[kk-1][i + 1]) : 3.0e38f;
            e[j] = __expf(mn - t);      // invalid / i<wb lanes -> 0
            s += e[j];
        }
        #pragma unroll
        for (int off = 16; off > 0; off >>= 1)
            s += __shfl_xor_sync(0xffffffffu, s, off);
        float inv = __fdividef(1.0f, s);
        #pragma unroll
        for (int j = 0; j < 8; j++) acc[j] += e[j] * inv;
    }

    #pragma unroll
    for (int j = 0; j < 8; j++) s_acc[w][l + 32*j] = acc[j];
    __syncthreads();
    if (tid < SEQ) {
        float sum = 0.0f;
        #pragma unroll
        for (int ww = 0; ww < PCT/32; ww++) sum += s_acc[ww][tid];
        g_part[b][blk][tid] = sum;
    }
}

// out[b][i] = (sum of partials + k0 term) / exact mask count
__global__ __launch_bounds__(256) void finalize_kernel(float* __restrict__ out)
{
    const int b = blockIdx.x, i = threadIdx.x;
    float num = (i == SEQ - 1) ? (float)SEQ : 0.0f;
    #pragma unroll
    for (int p = 0; p < PCB; p++) num += g_part[b][p][i];
    int m = min(KMAX - 1, SEQ - 1 - i);
    float cnt = (float)((i + 1) * m + ((i == SEQ - 1) ? SEQ : 0));
    out[b*SEQ + i] = num / cnt;
}

// ============================================================
extern "C" void kernel_launch(void* const* d_in, const int* in_sizes, int n_in,
                              void* d_out, int out_size)
{
    const float* x  = (const float*)d_in[0];
    const float* W0 = (const float*)d_in[1];
    const float* b0 = (const float*)d_in[2];
    const float* W1 = (const float*)d_in[3];
    const float* b1 = (const float*)d_in[4];
    float* out = (float*)d_out;

    static float* p_h = nullptr;
    static float* p_z = nullptr;
    if (!p_h) {
        cudaGetSymbolAddress((void**)&p_h, g_h);
        cudaGetSymbolAddress((void**)&p_z, g_z);
    }

    gemm_kernel<1><<<dim3(F1/64, (BATCH*SEQ)/64), 256>>>(x,   W0, b0, p_h, BATCH*SEQ, F1, F0);
    gemm_kernel<0><<<dim3(F2/64, (BATCH*SEQ)/64), 256>>>(p_h, W1, b1, p_z, BATCH*SEQ, F2, F1);
    syrk_kernel    <<<dim3(SEQ/64, SEQ/64, BATCH), 256>>>();
    scanP_kernel   <<<dim3(NSEG, BATCH), 256>>>();
    phaseC_kernel  <<<dim3(BATCH, PCB), PCT>>>();
    finalize_kernel<<<BATCH, SEQ>>>(out);
}